// round 15
// baseline (speedup 1.0000x reference)
#include <cuda_runtime.h>

#define LOG2E 1.4426950408889634f
#define LN2   0.6931471805599453f
#define CHUNK 32
#define MAXC  32         // ceil(1023/32)
#define NPK   33         // 0..15 = q-pairs (backward), 16..31 = r-pairs (forward), 32 = gathers

__device__ float g_Erow[64][64];        // exp(K[i][j]) row-major
__device__ float g_Ecol[64][64];        // g_Ecol[j][i] = exp(K[i][j])
__device__ float g_qv[1024][MAXC][64];
__device__ float g_rv[1024][MAXC - 1][64];
__device__ float g_qoff[1024][MAXC];
__device__ float g_roff[1024][MAXC - 1];
__device__ float g_seqs[1024];
__device__ float g_partial[1024];
__device__ unsigned int g_done[1024];   // zero-init; self-resetting
__device__ unsigned int g_count = 0;

static __device__ __forceinline__ float ex2f_(float x) {
    float y; asm("ex2.approx.ftz.f32 %0, %1;" : "=f"(y) : "f"(x)); return y;
}
static __device__ __forceinline__ float lg2f_(float x) {
    float y; asm("lg2.approx.ftz.f32 %0, %1;" : "=f"(y) : "f"(x)); return y;
}
static __device__ __forceinline__ unsigned long long fma2_(unsigned long long a,
                                                           unsigned long long b,
                                                           unsigned long long c) {
    unsigned long long d;
    asm("fma.rn.f32x2 %0, %1, %2, %3;" : "=l"(d) : "l"(a), "l"(b), "l"(c));
    return d;
}
static __device__ __forceinline__ unsigned long long addx2_(unsigned long long a,
                                                            unsigned long long b) {
    unsigned long long d;
    asm("add.rn.f32x2 %0, %1, %2;" : "=l"(d) : "l"(a), "l"(b));
    return d;
}
static __device__ __forceinline__ void unpack2_(unsigned long long v, float& lo, float& hi) {
    asm("mov.b64 {%0, %1}, %2;" : "=f"(lo), "=f"(hi) : "l"(v));
}
static __device__ __forceinline__ float wredsum_(float v) {
#pragma unroll
    for (int m = 16; m > 0; m >>= 1) v += __shfl_xor_sync(0xffffffffu, v, m);
    return v;
}

// Pre-kernel: exponentiate the chain kernel once per launch, both layouts.
__global__ void prep_E_kernel(const float* __restrict__ K) {
    int i = blockIdx.x * 256 + threadIdx.x;   // 16 blocks x 256 = 4096
    if (i < 4096) {
        float v = ex2f_(K[i] * LOG2E);
        int r = i >> 6, c = i & 63;
        g_Erow[r][c] = v;
        g_Ecol[c][r] = v;
    }
}

// Half-contraction over this warp's 32-index half of BUF for states jO and jF.
#define MACHP(BUF, SO, SF)                                                  \
    {                                                                       \
        const ulonglong2* wv_ = (const ulonglong2*)(BUF);                   \
        unsigned long long o0_=0ull, o1_=0ull, f0_=0ull, f1_=0ull;          \
        _Pragma("unroll")                                                   \
        for (int k_ = 0; k_ < 8; k_++) {                                    \
            ulonglong2 q_ = wv_[k_];                                        \
            o0_ = fma2_(q_.x, eO[2*k_],     o0_);                           \
            o1_ = fma2_(q_.y, eO[2*k_ + 1], o1_);                           \
            f0_ = fma2_(q_.x, eF[2*k_],     f0_);                           \
            f1_ = fma2_(q_.y, eF[2*k_ + 1], f1_);                           \
        }                                                                   \
        float lo_, hi_;                                                     \
        unpack2_(addx2_(o0_, o1_), lo_, hi_); SO = lo_ + hi_;               \
        unpack2_(addx2_(f0_, f1_), lo_, hi_); SF = lo_ + hi_;               \
    }

// ---------- paired bodies (two same-orientation chains, one barrier) ----------
#define BPAIR(UU, PB)                                                       \
    {                                                                       \
        float pA_, pB_;                                                     \
        if (PB) {                                                           \
            float DA_ = dshA[(PB)^1]; float lA_ = lg2f_(DA_); loffA += lA_; \
            pA_ = ex2f_(fmaf(pfA[UU], LOG2E, -lA_));                        \
            float DB_ = dshB[(PB)^1]; float lB_ = lg2f_(DB_); loffB += lB_; \
            pB_ = ex2f_(fmaf(pfB[UU], LOG2E, -lB_));                        \
        } else {                                                            \
            pA_ = ex2f_(pfA[UU] * LOG2E);                                   \
            pB_ = ex2f_(pfB[UU] * LOG2E);                                   \
        }                                                                   \
        pfA[UU] = *(const float*)(potc + offA); offA = max(offA-256, offloA);\
        pfB[UU] = *(const float*)(potc + offB); offB = max(offB-256, offloB);\
        float yA_ = xA * pA_, yB_ = xB * pB_;                               \
        wshA[jO] = yA_; wshB[jO] = yB_;                                     \
        if (jO == 0) { dshA[PB] = yA_; dshB[PB] = yB_; }                    \
        __syncwarp();                                                       \
        float sOA_, sFA_, sOB_, sFB_;                                       \
        MACHP(&wshA[h << 5], sOA_, sFA_)                                    \
        MACHP(&wshB[h << 5], sOB_, sFB_)                                    \
        ppA[PB][jF] = sFA_; ppB[PB][jF] = sFB_;                             \
        __syncthreads();                                                    \
        xA = sOA_ + ppA[PB][jO]; xB = sOB_ + ppB[PB][jO];                   \
    }

#define FPAIR(UU, PB)                                                       \
    {                                                                       \
        float pA_, pB_;                                                     \
        if (PB) {                                                           \
            float DA_ = dshA[1]; float lA_ = lg2f_(DA_); loffA += lA_;      \
            pA_ = ex2f_(fmaf(pfA[UU], LOG2E, -lA_));                        \
            float DB_ = dshB[1]; float lB_ = lg2f_(DB_); loffB += lB_;      \
            pB_ = ex2f_(fmaf(pfB[UU], LOG2E, -lB_));                        \
        } else {                                                            \
            pA_ = ex2f_(pfA[UU] * LOG2E);                                   \
            pB_ = ex2f_(pfB[UU] * LOG2E);                                   \
        }                                                                   \
        pfA[UU] = *(const float*)(potc + offA); offA = min(offA+256, offhiA);\
        pfB[UU] = *(const float*)(potc + offB); offB = min(offB+256, offhiB);\
        float sOA_, sFA_, sOB_, sFB_;                                       \
        MACHP(&wshA[h << 5], sOA_, sFA_)                                    \
        MACHP(&wshB[h << 5], sOB_, sFB_)                                    \
        ppA[PB][jF] = sFA_; ppB[PB][jF] = sFB_;                             \
        __syncthreads();                                                    \
        float vA_ = (sOA_ + ppA[PB][jO]) * pA_;                             \
        float vB_ = (sOB_ + ppB[PB][jO]) * pB_;                             \
        wshA[jO] = vA_; wshB[jO] = vB_;                                     \
        if (jO == 0) { dshA[PB] = vA_; dshB[PB] = vB_; }                    \
        __syncwarp();                                                       \
    }

// ---------- single-chain bodies (chain A only; parity-normed) ----------
#define BSING(UU, PB)                                                       \
    {                                                                       \
        float pA_;                                                          \
        if (PB) {                                                           \
            float D_ = dshA[(PB)^1]; float lD_ = lg2f_(D_); loffA += lD_;   \
            pA_ = ex2f_(fmaf(pfA[UU], LOG2E, -lD_));                        \
        } else {                                                            \
            pA_ = ex2f_(pfA[UU] * LOG2E);                                   \
        }                                                                   \
        pfA[UU] = *(const float*)(potc + offA); offA = max(offA-256, offloA);\
        float y_ = xA * pA_;                                                \
        wshA[jO] = y_;                                                      \
        if (jO == 0) dshA[PB] = y_;                                         \
        __syncwarp();                                                       \
        float sO_, sF_;                                                     \
        MACHP(&wshA[h << 5], sO_, sF_)                                      \
        ppA[PB][jF] = sF_;                                                  \
        __syncthreads();                                                    \
        xA = sO_ + ppA[PB][jO];                                             \
    }

#define FSING(UU, PB)                                                       \
    {                                                                       \
        float pA_;                                                          \
        if (PB) {                                                           \
            float D_ = dshA[1]; float lD_ = lg2f_(D_); loffA += lD_;        \
            pA_ = ex2f_(fmaf(pfA[UU], LOG2E, -lD_));                        \
        } else {                                                            \
            pA_ = ex2f_(pfA[UU] * LOG2E);                                   \
        }                                                                   \
        pfA[UU] = *(const float*)(potc + offA); offA = min(offA+256, offhiA);\
        float sO_, sF_;                                                     \
        MACHP(&wshA[h << 5], sO_, sF_)                                      \
        ppA[PB][jF] = sF_;                                                  \
        __syncthreads();                                                    \
        float v_ = (sO_ + ppA[PB][jO]) * pA_;                               \
        wshA[jO] = v_;                                                      \
        if (jO == 0) dshA[PB] = v_;                                         \
        __syncwarp();                                                       \
    }

// ---------- tail bodies (chain A, always-norm, ping-ponged slots via tp) ----------
#define BTAIL(TQ)                                                           \
    {                                                                       \
        float D_ = dshA[tp ^ 1]; float lD_ = lg2f_(D_); loffA += lD_;       \
        float p_ = ex2f_(fmaf(TQ, LOG2E, -lD_));                            \
        TQ = *(const float*)(potc + offT); offT = max(offT-256, offloA);    \
        float y_ = xA * p_;                                                 \
        wshA[jO] = y_;                                                      \
        if (jO == 0) dshA[tp] = y_;                                         \
        __syncwarp();                                                       \
        float sO_, sF_;                                                     \
        MACHP(&wshA[h << 5], sO_, sF_)                                      \
        ppA[tp][jF] = sF_;                                                  \
        __syncthreads();                                                    \
        xA = sO_ + ppA[tp][jO];                                             \
        tp ^= 1;                                                            \
    }

#define FTAIL(TQ)                                                           \
    {                                                                       \
        float D_ = dshA[tp ^ 1]; float lD_ = lg2f_(D_); loffA += lD_;       \
        float p_ = ex2f_(fmaf(TQ, LOG2E, -lD_));                            \
        TQ = *(const float*)(potc + offT); offT = min(offT+256, offhiA);    \
        float sO_, sF_;                                                     \
        MACHP(&wshA[h << 5], sO_, sF_)                                      \
        ppA[tp][jF] = sF_;                                                  \
        __syncthreads();                                                    \
        float v_ = (sO_ + ppA[tp][jO]) * p_;                                \
        wshA[jO] = v_;                                                      \
        if (jO == 0) dshA[tp] = v_;                                         \
        __syncwarp();                                                       \
        tp ^= 1;                                                            \
    }

// One CTA (64 threads, 2 warps) per (batch, task-pair).
__global__ __launch_bounds__(64, 8) void crf_all_kernel(
    const float* __restrict__ pot,     // [B, T, 64]
    const int*   __restrict__ tags,    // [B, T]
    const int*   __restrict__ seqlen,  // [B]
    const float* __restrict__ K,       // [64, 64]
    const float* __restrict__ sw,      // [B]
    float*       __restrict__ out,
    int T, int B)
{
    const int b    = blockIdx.x / NPK;
    const int k    = blockIdx.x % NPK;
    const int tid  = threadIdx.x;
    const int lane = tid & 31;
    const int h    = tid >> 5;
    const int jO   = (h << 5) + lane;
    const int jF   = ((1 - h) << 5) + lane;

    int L = seqlen[b];
    if (L > T) L = T;
    if (L < 1) L = 1;
    const int M  = L - 1;
    const int nc = (M + CHUNK - 1) / CHUNK;

    const float* potb = pot + (size_t)b * T * 64;
    const char*  potc = (const char*)potb;

    __shared__ __align__(16) float wshA[64];
    __shared__ __align__(16) float wshB[64];
    __shared__ float ppA[2][64], ppB[2][64];
    __shared__ float dshA[2], dshB[2];
    __shared__ float sred[64];

    int cnt = 1;

    if (k == NPK - 1) {
        // ================= sequence-score gathers =================
        const int* tagb = tags + (size_t)b * T;
        float acc = 0.f;
        for (int t = tid; t < T; t += 64) {
            if (t < L) {
                int tg = tagb[t];
                acc += __ldg(potb + (size_t)t * 64 + tg);
                if (t >= 1) acc += __ldg(K + tagb[t - 1] * 64 + tg);
            }
        }
        sred[tid] = acc;
        __syncthreads();
        if (h == 0) {
            float v = sred[lane] + sred[lane + 32];
            v = wredsum_(v);
            if (lane == 0) g_seqs[b] = v;
        }
    } else {
        const bool is_q = (k < 16);
        const int  kp   = is_q ? k : (k - 16);
        const int  cA   = 2 * kp + 1;
        const int  cB   = 2 * kp + 2;
        const int  cmax = is_q ? nc : (nc - 1);
        const bool validA = (cA <= cmax);
        const bool validB = (cB <= cmax);
        if (!validA) return;          // no arrival
        cnt = validB ? 2 : 1;

        const int aA = (cA - 1) * CHUNK + 1, bendA = min(cA * CHUNK, M);
        const int aB = (cB - 1) * CHUNK + 1, bendB = min(cB * CHUNK, M);
        const int nsA = bendA - aA + 1;
        const int nsB = validB ? (bendB - aB + 1) : 0;
        const int s4 = jO << 2;
        const int offloA = aA * 256 + s4, offhiA = bendA * 256 + s4;
        const int offloB = aB * 256 + s4, offhiB = bendB * 256 + s4;

        // E registers from the precomputed tables: packed-pair layout comes for
        // free because two adjacent floats in memory = one f32x2 register pair.
        unsigned long long eO[16], eF[16];
        {
            const ulonglong2* epO = is_q
                ? (const ulonglong2*)&g_Erow[jO][h << 5]
                : (const ulonglong2*)&g_Ecol[jO][h << 5];
            const ulonglong2* epF = is_q
                ? (const ulonglong2*)&g_Erow[jF][h << 5]
                : (const ulonglong2*)&g_Ecol[jF][h << 5];
#pragma unroll
            for (int m = 0; m < 8; m++) {
                ulonglong2 qO = epO[m], qF = epF[m];
                eO[2*m] = qO.x; eO[2*m+1] = qO.y;
                eF[2*m] = qF.x; eF[2*m+1] = qF.y;
            }
        }

        float loffA = 0.f, loffB = 0.f;
        float pfA[4], pfB[4];
        int tp = 0;

        if (tid == 0) { dshA[0] = dshA[1] = 1.0f; dshB[0] = dshB[1] = 1.0f; }

        if (is_q) {
            // ======== backward chains ========
            float xA = 1.0f, xB = 1.0f;
#pragma unroll
            for (int u = 0; u < 4; u++) {
                int rA = bendA - u; if (rA < aA) rA = aA;
                pfA[u] = potb[(size_t)rA * 64 + jO];
                int rB = validB ? (bendB - u) : aA;
                if (rB < aB) rB = aB;
                pfB[u] = validB ? potb[(size_t)rB * 64 + jO] : 0.f;
            }
            int offA = (bendA - 4) * 256 + s4; if (offA < offloA) offA = offloA;
            int offB = validB ? ((bendB - 4) * 256 + s4) : offloB;
            if (offB < offloB) offB = offloB;
            __syncthreads();

            if (validB) {
                int n4 = nsB >> 2;
                for (int it = 0; it < n4; it++) {
                    BPAIR(0, 0) BPAIR(1, 1) BPAIR(2, 0) BPAIR(3, 1)
                }
                int rem = nsB & 3;
                if (rem > 0) BPAIR(0, 0)
                if (rem > 1) BPAIR(1, 1)
                if (rem > 2) BPAIR(2, 0)

                g_qv[b][cB - 1][jO] = xB;
                if (tid == 0) g_qoff[b][cB - 1] = loffB;

                // tail for A: remaining nsA - nsB bodies (A always full here)
                int rem2 = nsA - nsB;
                if (rem2 > 0) {
                    int tn = bendA - nsB;
                    int r0 = tn, r1 = tn - 1;
                    if (r1 < aA) r1 = aA;
                    float tq0 = potb[(size_t)r0 * 64 + jO];
                    float tq1 = potb[(size_t)r1 * 64 + jO];
                    int offT = (tn - 2) * 256 + s4; if (offT < offloA) offT = offloA;
                    int s = 0;
                    for (; s + 2 <= rem2; s += 2) { BTAIL(tq0) BTAIL(tq1) }
                    if (s < rem2) BTAIL(tq0)
                }
            } else {
                int n4 = nsA >> 2;
                for (int it = 0; it < n4; it++) {
                    BSING(0, 0) BSING(1, 1) BSING(2, 0) BSING(3, 1)
                }
                int rem = nsA & 3;
                if (rem > 0) BSING(0, 0)
                if (rem > 1) BSING(1, 1)
                if (rem > 2) BSING(2, 0)
            }

            g_qv[b][cA - 1][jO] = xA;
            if (tid == 0) g_qoff[b][cA - 1] = loffA;
        } else {
            // ======== forward chains ========
            wshA[jO] = 1.0f; wshB[jO] = 1.0f;
#pragma unroll
            for (int u = 0; u < 4; u++) {
                int rA = aA + u; if (rA > bendA) rA = bendA;
                pfA[u] = potb[(size_t)rA * 64 + jO];
                int rB = aB + u; if (rB > bendB) rB = bendB;
                pfB[u] = validB ? potb[(size_t)rB * 64 + jO] : 0.f;
            }
            int offA = (aA + 4) * 256 + s4; if (offA > offhiA) offA = offhiA;
            int offB = validB ? ((aB + 4) * 256 + s4) : offloB;
            if (offB > offhiB) offB = offhiB;
            __syncthreads();

            if (validB) {
                int n4 = nsB >> 2;
                for (int it = 0; it < n4; it++) {
                    FPAIR(0, 0) FPAIR(1, 1) FPAIR(2, 0) FPAIR(3, 1)
                }
                int rem = nsB & 3;
                if (rem > 0) FPAIR(0, 0)
                if (rem > 1) FPAIR(1, 1)
                if (rem > 2) FPAIR(2, 0)

                g_rv[b][cB - 1][jO] = wshB[jO];
                if (tid == 0) g_roff[b][cB - 1] = loffB;

                int rem2 = nsA - nsB;
                if (rem2 > 0) {
                    int tn = aA + nsB;
                    int r0 = tn, r1 = tn + 1;
                    if (r1 > bendA) r1 = bendA;
                    float tq0 = potb[(size_t)r0 * 64 + jO];
                    float tq1 = potb[(size_t)r1 * 64 + jO];
                    int offT = (tn + 2) * 256 + s4; if (offT > offhiA) offT = offhiA;
                    int s = 0;
                    for (; s + 2 <= rem2; s += 2) { FTAIL(tq0) FTAIL(tq1) }
                    if (s < rem2) FTAIL(tq0)
                }
            } else {
                int n4 = nsA >> 2;
                for (int it = 0; it < n4; it++) {
                    FSING(0, 0) FSING(1, 1) FSING(2, 0) FSING(3, 1)
                }
                int rem = nsA & 3;
                if (rem > 0) FSING(0, 0)
                if (rem > 1) FSING(1, 1)
                if (rem > 2) FSING(2, 0)
            }

            g_rv[b][cA - 1][jO] = wshA[jO];
            if (tid == 0) g_roff[b][cA - 1] = loffA;
        }
    }

    // ================= arrival + inline stitch (last task of batch) =================
    __threadfence();
    __syncthreads();
    if (h != 0) return;

    const unsigned int ntasks = 1u + (unsigned)nc + (unsigned)(nc > 0 ? nc - 1 : 0);
    unsigned int old = 0;
    if (lane == 0) old = atomicAdd(&g_done[b], (unsigned)cnt);
    old = __shfl_sync(0xffffffffu, old, 0);
    if (old + (unsigned)cnt != ntasks) return;

    if (lane == 0) g_done[b] = 0;    // reset for graph replay
    __threadfence();

    float p0lo = ex2f_(potb[lane] * LOG2E);
    float p0hi = ex2f_(potb[lane + 32] * LOG2E);

    float log2A;
    if (nc == 0) {
        log2A = lg2f_(wredsum_(p0lo + p0hi));
    } else {
        float d1 = wredsum_(p0lo * g_qv[b][0][lane] + p0hi * g_qv[b][0][lane + 32]);
        log2A = lg2f_(d1) + g_qoff[b][0];
        for (int cc = 2; cc <= nc; cc++) {
            float d = wredsum_(g_rv[b][cc-2][lane]      * g_qv[b][cc-1][lane] +
                               g_rv[b][cc-2][lane + 32] * g_qv[b][cc-1][lane + 32]);
            float sig = wredsum_(g_qv[b][cc-2][lane] + g_qv[b][cc-2][lane + 32]);
            log2A += lg2f_(d) + g_roff[b][cc-2] + g_qoff[b][cc-1]
                   - lg2f_(sig) - g_qoff[b][cc-2];
        }
    }

    if (lane == 0) {
        g_partial[b] = -(g_seqs[b] - log2A * LN2) * sw[b];
        __threadfence();
    }
    __syncwarp();

    unsigned int o2 = 0;
    if (lane == 0) o2 = atomicAdd(&g_count, 1);
    o2 = __shfl_sync(0xffffffffu, o2, 0);
    if (o2 == (unsigned)B - 1) {
        if (lane == 0) { g_count = 0; __threadfence(); }
        __syncwarp();
        float tot = 0.f;
        for (int i = lane; i < B; i += 32) tot += g_partial[i];
        tot = wredsum_(tot);
        if (lane == 0) *out = tot / (float)B;
    }
}

extern "C" void kernel_launch(void* const* d_in, const int* in_sizes, int n_in,
                              void* d_out, int out_size) {
    const float* pot    = (const float*)d_in[0];
    const int*   tags   = (const int*)d_in[1];
    const int*   seqlen = (const int*)d_in[2];
    const float* K      = (const float*)d_in[3];
    const float* sw     = (const float*)d_in[4];

    int B = in_sizes[2];            // sequence_length element count
    int T = in_sizes[1] / B;        // tags is [B, T]

    prep_E_kernel<<<16, 256>>>(K);
    crf_all_kernel<<<B * NPK, 64>>>(pot, tags, seqlen, K, sw, (float*)d_out, T, B);
}

// round 16
// speedup vs baseline: 1.0035x; 1.0035x over previous
#include <cuda_runtime.h>

#define LOG2E 1.4426950408889634f
#define LN2   0.6931471805599453f
#define CHUNK 32
#define MAXC  32         // ceil(1023/32)
#define NPK   33         // 0..15 = q-pairs (backward), 16..31 = r-pairs (forward), 32 = gathers
#define NTHR  128

__device__ float g_qv[1024][MAXC][64];
__device__ float g_rv[1024][MAXC - 1][64];
__device__ float g_qoff[1024][MAXC];
__device__ float g_roff[1024][MAXC - 1];
__device__ float g_seqs[1024];
__device__ float g_partial[1024];
__device__ unsigned int g_done[1024];   // zero-init; self-resetting
__device__ unsigned int g_count = 0;

static __device__ __forceinline__ float ex2f_(float x) {
    float y; asm("ex2.approx.ftz.f32 %0, %1;" : "=f"(y) : "f"(x)); return y;
}
static __device__ __forceinline__ float lg2f_(float x) {
    float y; asm("lg2.approx.ftz.f32 %0, %1;" : "=f"(y) : "f"(x)); return y;
}
static __device__ __forceinline__ unsigned long long pack2_(float lo, float hi) {
    unsigned long long d;
    asm("mov.b64 %0, {%1, %2};" : "=l"(d) : "f"(lo), "f"(hi));
    return d;
}
static __device__ __forceinline__ unsigned long long fma2_(unsigned long long a,
                                                           unsigned long long b,
                                                           unsigned long long c) {
    unsigned long long d;
    asm("fma.rn.f32x2 %0, %1, %2, %3;" : "=l"(d) : "l"(a), "l"(b), "l"(c));
    return d;
}
static __device__ __forceinline__ unsigned long long addx2_(unsigned long long a,
                                                            unsigned long long b) {
    unsigned long long d;
    asm("add.rn.f32x2 %0, %1, %2;" : "=l"(d) : "l"(a), "l"(b));
    return d;
}
static __device__ __forceinline__ void unpack2_(unsigned long long v, float& lo, float& hi) {
    asm("mov.b64 {%0, %1}, %2;" : "=f"(lo), "=f"(hi) : "l"(v));
}
static __device__ __forceinline__ float wredsum_(float v) {
#pragma unroll
    for (int m = 16; m > 0; m >>= 1) v += __shfl_xor_sync(0xffffffffu, v, m);
    return v;
}

// MAC over this thread's 16-i slice for states sM0/sM1 of buffer WS. 16 FFMA2.
#define MAC16(WS, S0, S1)                                                   \
    {                                                                       \
        const ulonglong2* wv_ = (const ulonglong2*)(&(WS)[i0]);             \
        unsigned long long a0_=0ull, a1_=0ull, b0_=0ull, b1_=0ull;          \
        _Pragma("unroll")                                                   \
        for (int k_ = 0; k_ < 4; k_++) {                                    \
            ulonglong2 q_ = wv_[k_];                                        \
            a0_ = fma2_(q_.x, eO[2*k_],     a0_);                           \
            a1_ = fma2_(q_.y, eO[2*k_ + 1], a1_);                           \
            b0_ = fma2_(q_.x, eP[2*k_],     b0_);                           \
            b1_ = fma2_(q_.y, eP[2*k_ + 1], b1_);                           \
        }                                                                   \
        float lo_, hi_;                                                     \
        unpack2_(addx2_(a0_, a1_), lo_, hi_); S0 = lo_ + hi_;               \
        unpack2_(addx2_(b0_, b1_), lo_, hi_); S1 = lo_ + hi_;               \
    }

// ---- backward pair body: phase0(scale+store y) BAR MAC+pp BAR combine ----
#define BPB(UU, PB)                                                         \
    {                                                                       \
        {                                                                   \
            float p_;                                                       \
            if (PB) {                                                       \
                float lD_ = lg2f_(myDsh[(PB)^1]); loffv += lD_;             \
                p_ = ex2f_(fmaf(pf[UU], LOG2E, -lD_));                      \
            } else {                                                        \
                p_ = ex2f_(pf[UU] * LOG2E);                                 \
            }                                                               \
            pf[UU] = *(const float*)(potc + off);                           \
            off = max(off - 256, offloM);                                   \
            float y_ = xreg * p_;                                           \
            myW[cs] = y_;                                                   \
            if (cs == 0) myDsh[PB] = y_;                                    \
        }                                                                   \
        __syncthreads();                                                    \
        float s0A_, s1A_, s0B_, s1B_;                                       \
        MAC16(wsh[0], s0A_, s1A_)                                           \
        MAC16(wsh[1], s0B_, s1B_)                                           \
        pp[0][sM0*5 + wq] = s0A_; pp[0][sM1*5 + wq] = s1A_;                 \
        pp[1][sM0*5 + wq] = s0B_; pp[1][sM1*5 + wq] = s1B_;                 \
        __syncthreads();                                                    \
        xreg = myPP[cs5] + myPP[cs5+1] + myPP[cs5+2] + myPP[cs5+3];         \
    }

// backward single (chain A only)
#define BSB(UU, PB)                                                         \
    {                                                                       \
        if (actA) {                                                         \
            float p_;                                                       \
            if (PB) {                                                       \
                float lD_ = lg2f_(dsh[0][(PB)^1]); loffv += lD_;            \
                p_ = ex2f_(fmaf(pf[UU], LOG2E, -lD_));                      \
            } else {                                                        \
                p_ = ex2f_(pf[UU] * LOG2E);                                 \
            }                                                               \
            pf[UU] = *(const float*)(potc + off);                           \
            off = max(off - 256, offloM);                                   \
            float y_ = xreg * p_;                                           \
            wsh[0][cs] = y_;                                                \
            if (cs == 0) dsh[0][PB] = y_;                                   \
        }                                                                   \
        __syncthreads();                                                    \
        float s0_, s1_;                                                     \
        MAC16(wsh[0], s0_, s1_)                                             \
        pp[0][sM0*5 + wq] = s0_; pp[0][sM1*5 + wq] = s1_;                   \
        __syncthreads();                                                    \
        if (actA) xreg = pp[0][cs5] + pp[0][cs5+1] + pp[0][cs5+2] + pp[0][cs5+3]; \
    }

// backward tail body (chain A, always-norm, runtime slot tp)
#define BT(TQ)                                                              \
    {                                                                       \
        if (actA) {                                                         \
            float lD_ = lg2f_(dsh[0][tp ^ 1]); loffv += lD_;                \
            float p_ = ex2f_(fmaf(TQ, LOG2E, -lD_));                        \
            TQ = *(const float*)(potc + offT);                              \
            offT = max(offT - 256, offloT);                                 \
            float y_ = xreg * p_;                                           \
            wsh[0][cs] = y_;                                                \
            if (cs == 0) dsh[0][tp] = y_;                                   \
        }                                                                   \
        __syncthreads();                                                    \
        float s0_, s1_;                                                     \
        MAC16(wsh[0], s0_, s1_)                                             \
        pp[0][sM0*5 + wq] = s0_; pp[0][sM1*5 + wq] = s1_;                   \
        __syncthreads();                                                    \
        if (actA) xreg = pp[0][cs5] + pp[0][cs5+1] + pp[0][cs5+2] + pp[0][cs5+3]; \
        tp ^= 1;                                                            \
    }

// ---- forward pair body: MAC+pp BAR combine(+store w) BAR ----
#define FPB(UU, RD, WR, NORM)                                               \
    {                                                                       \
        float s0A_, s1A_, s0B_, s1B_;                                       \
        MAC16(wsh[0], s0A_, s1A_)                                           \
        MAC16(wsh[1], s0B_, s1B_)                                           \
        pp[0][sM0*5 + wq] = s0A_; pp[0][sM1*5 + wq] = s1A_;                 \
        pp[1][sM0*5 + wq] = s0B_; pp[1][sM1*5 + wq] = s1B_;                 \
        __syncthreads();                                                    \
        {                                                                   \
            float part_ = myPP[cs5] + myPP[cs5+1] + myPP[cs5+2] + myPP[cs5+3]; \
            float p_;                                                       \
            if (NORM) {                                                     \
                float l_ = lg2f_(myDsh[RD]); loffv += l_;                   \
                p_ = ex2f_(fmaf(pf[UU], LOG2E, -l_));                       \
            } else {                                                        \
                p_ = ex2f_(pf[UU] * LOG2E);                                 \
            }                                                               \
            pf[UU] = *(const float*)(potc + off);                           \
            off = min(off + 256, offhiM);                                   \
            float v_ = part_ * p_;                                          \
            myW[cs] = v_;                                                   \
            if (cs == 0 && NORM) myDsh[WR] = v_;                            \
        }                                                                   \
        __syncthreads();                                                    \
    }

// forward single (chain A only)
#define FSB(UU, RD, WR, NORM)                                               \
    {                                                                       \
        float s0_, s1_;                                                     \
        MAC16(wsh[0], s0_, s1_)                                             \
        pp[0][sM0*5 + wq] = s0_; pp[0][sM1*5 + wq] = s1_;                   \
        __syncthreads();                                                    \
        if (actA) {                                                         \
            float part_ = pp[0][cs5] + pp[0][cs5+1] + pp[0][cs5+2] + pp[0][cs5+3]; \
            float p_;                                                       \
            if (NORM) {                                                     \
                float l_ = lg2f_(dsh[0][RD]); loffv += l_;                  \
                p_ = ex2f_(fmaf(pf[UU], LOG2E, -l_));                       \
            } else {                                                        \
                p_ = ex2f_(pf[UU] * LOG2E);                                 \
            }                                                               \
            pf[UU] = *(const float*)(potc + off);                           \
            off = min(off + 256, offhiM);                                   \
            float v_ = part_ * p_;                                          \
            wsh[0][cs] = v_;                                                \
            if (cs == 0 && NORM) dsh[0][WR] = v_;                           \
        }                                                                   \
        __syncthreads();                                                    \
    }

// One CTA (128 threads, 4 warps) per (batch, task-pair).
// MAC role: warp wq owns i-slice [16wq,16wq+16), lane -> states (lane, lane+32).
// Combine role: thread t owns (chain t>>6, state t&63).
__global__ __launch_bounds__(NTHR, 5) void crf_all_kernel(
    const float* __restrict__ pot,     // [B, T, 64]
    const int*   __restrict__ tags,    // [B, T]
    const int*   __restrict__ seqlen,  // [B]
    const float* __restrict__ K,       // [64, 64]
    const float* __restrict__ sw,      // [B]
    float*       __restrict__ out,
    int T, int B)
{
    const int b    = blockIdx.x / NPK;
    const int k    = blockIdx.x % NPK;
    const int tid  = threadIdx.x;
    const int lane = tid & 31;
    const int wq   = tid >> 5;
    const int i0   = wq << 4;
    const int sM0  = lane, sM1 = lane + 32;
    const int cch  = tid >> 6;
    const int cs   = tid & 63;
    const int cs5  = cs * 5;

    int L = seqlen[b];
    if (L > T) L = T;
    if (L < 1) L = 1;
    const int M  = L - 1;
    const int nc = (M + CHUNK - 1) / CHUNK;

    const float* potb = pot + (size_t)b * T * 64;
    const char*  potc = (const char*)potb;

    __shared__ __align__(16) float wsh[2][64];
    __shared__ float pp[2][320];        // [chain][state*5 + warp], padded: conflict-free
    __shared__ float dsh[2][2];         // [chain][slot]
    __shared__ float sred[NTHR];

    int cnt = 1;

    if (k == NPK - 1) {
        // ================= sequence-score gathers =================
        const int* tagb = tags + (size_t)b * T;
        float acc = 0.f;
        for (int t = tid; t < T; t += NTHR) {
            if (t < L) {
                int tg = tagb[t];
                acc += __ldg(potb + (size_t)t * 64 + tg);
                if (t >= 1) acc += __ldg(K + tagb[t - 1] * 64 + tg);
            }
        }
        sred[tid] = acc;
        __syncthreads();
        if (tid < 32) {
            float v = sred[lane] + sred[lane + 32] + sred[lane + 64] + sred[lane + 96];
            v = wredsum_(v);
            if (lane == 0) g_seqs[b] = v;
        }
    } else {
        const bool is_q = (k < 16);
        const int  kp   = is_q ? k : (k - 16);
        const int  cA   = 2 * kp + 1;
        const int  cB   = 2 * kp + 2;
        const int  cmax = is_q ? nc : (nc - 1);
        const bool validA = (cA <= cmax);
        const bool validB = (cB <= cmax);
        if (!validA) return;          // whole CTA, uniform
        cnt = validB ? 2 : 1;

        const int aA = (cA - 1) * CHUNK + 1, bendA = min(cA * CHUNK, M);
        int       aB = (cB - 1) * CHUNK + 1, bendB = min(cB * CHUNK, M);
        if (!validB) { aB = aA; bendB = bendA; }
        const int nsA = bendA - aA + 1;
        const int nsB = validB ? (bendB - aB + 1) : 0;

        const int aM    = cch ? aB : aA;
        const int bendM = cch ? bendB : bendA;
        const int s4    = cs << 2;
        const int offloM = aM * 256 + s4;
        const int offhiM = bendM * 256 + s4;

        const bool actA = (cch == 0);

        // E registers: 16-i slice for both MAC states (shared by chains A and B)
        unsigned long long eO[8], eP[8];
        if (is_q) {
            const float4* k0 = (const float4*)(K + sM0 * 64 + i0);
            const float4* k1 = (const float4*)(K + sM1 * 64 + i0);
#pragma unroll
            for (int m = 0; m < 4; m++) {
                float4 v0 = k0[m], v1 = k1[m];
                eO[2*m]   = pack2_(ex2f_(v0.x * LOG2E), ex2f_(v0.y * LOG2E));
                eO[2*m+1] = pack2_(ex2f_(v0.z * LOG2E), ex2f_(v0.w * LOG2E));
                eP[2*m]   = pack2_(ex2f_(v1.x * LOG2E), ex2f_(v1.y * LOG2E));
                eP[2*m+1] = pack2_(ex2f_(v1.z * LOG2E), ex2f_(v1.w * LOG2E));
            }
        } else {
#pragma unroll
            for (int m = 0; m < 4; m++) {
                int r = i0 + 4 * m;
                eO[2*m]   = pack2_(ex2f_(K[r * 64 + sM0]       * LOG2E),
                                   ex2f_(K[(r + 1) * 64 + sM0] * LOG2E));
                eO[2*m+1] = pack2_(ex2f_(K[(r + 2) * 64 + sM0] * LOG2E),
                                   ex2f_(K[(r + 3) * 64 + sM0] * LOG2E));
                eP[2*m]   = pack2_(ex2f_(K[r * 64 + sM1]       * LOG2E),
                                   ex2f_(K[(r + 1) * 64 + sM1] * LOG2E));
                eP[2*m+1] = pack2_(ex2f_(K[(r + 2) * 64 + sM1] * LOG2E),
                                   ex2f_(K[(r + 3) * 64 + sM1] * LOG2E));
            }
        }

        float* myW   = &wsh[cch][0];
        float* myPP  = &pp[cch][0];
        float* myDsh = &dsh[cch][0];

        float loffv = 0.f, xreg = 1.f;
        float pf[4];
        int off;

        if (tid == 0) { dsh[0][0] = dsh[0][1] = 1.f; dsh[1][0] = dsh[1][1] = 1.f; }

        if (is_q) {
            // ======== backward chains: q = Pi_{t=bend..a}(E diag p) 1 ========
            const bool actMe = validB || actA;
#pragma unroll
            for (int u = 0; u < 4; u++) {
                int r = bendM - u; if (r < aM) r = aM;
                pf[u] = actMe ? potb[(size_t)r * 64 + cs] : 0.f;
            }
            off = (bendM - 4) * 256 + s4; if (off < offloM) off = offloM;
            __syncthreads();

            if (validB) {
                int n4 = nsB >> 2, rem = nsB & 3;
                for (int it = 0; it < n4; it++) {
                    BPB(0, 0) BPB(1, 1) BPB(2, 0) BPB(3, 1)
                }
                if (rem > 0) BPB(0, 0)
                if (rem > 1) BPB(1, 1)
                if (rem > 2) BPB(2, 0)

                if (!actA) {
                    g_qv[b][cB - 1][cs] = xreg;
                    if (tid == 64) g_qoff[b][cB - 1] = loffv;
                }

                int rem2 = nsA - nsB;    // A full when B valid
                if (rem2 > 0) {
                    int tp = nsB & 1;
                    int tn = bendA - nsB;
                    int r1 = tn - 1; if (r1 < aA) r1 = aA;
                    const int offloT = aA * 256 + s4;
                    float tq0 = actA ? potb[(size_t)tn * 64 + cs] : 0.f;
                    float tq1 = actA ? potb[(size_t)r1 * 64 + cs] : 0.f;
                    int offT = (tn - 2) * 256 + s4; if (offT < offloT) offT = offloT;
                    int s = 0;
                    for (; s + 2 <= rem2; s += 2) { BT(tq0) BT(tq1) }
                    if (s < rem2) BT(tq0)
                }
            } else {
                int n4 = nsA >> 2, rem = nsA & 3;
                for (int it = 0; it < n4; it++) {
                    BSB(0, 0) BSB(1, 1) BSB(2, 0) BSB(3, 1)
                }
                if (rem > 0) BSB(0, 0)
                if (rem > 1) BSB(1, 1)
                if (rem > 2) BSB(2, 0)
            }

            if (actA) {
                g_qv[b][cA - 1][cs] = xreg;
                if (tid == 0) g_qoff[b][cA - 1] = loffv;
            }
        } else {
            // ======== forward chains: r^T = 1^T Pi_{t=a..bend}(E diag p) ========
            if (actA) wsh[0][cs] = 1.f;
            else if (validB) wsh[1][cs] = 1.f;
            const bool actMe = validB || actA;
#pragma unroll
            for (int u = 0; u < 4; u++) {
                int r = aM + u; if (r > bendM) r = bendM;
                pf[u] = actMe ? potb[(size_t)r * 64 + cs] : 0.f;
            }
            off = (aM + 4) * 256 + s4; if (off > offhiM) off = offhiM;
            __syncthreads();

            if (validB) {
                int n4 = nsB >> 2, rem = nsB & 3;   // r-chunks are always full (32)
                for (int it = 0; it < n4; it++) {
                    FPB(0, 0, 0, 0) FPB(1, 1, 0, 1) FPB(2, 0, 0, 0) FPB(3, 0, 1, 1)
                }
                if (rem > 0) FPB(0, 0, 0, 0)
                if (rem > 1) FPB(1, 1, 0, 1)
                if (rem > 2) FPB(2, 0, 0, 0)

                if (actA) {
                    g_rv[b][cA - 1][cs] = wsh[0][cs];
                    if (tid == 0) g_roff[b][cA - 1] = loffv;
                } else {
                    g_rv[b][cB - 1][cs] = wsh[1][cs];
                    if (tid == 64) g_roff[b][cB - 1] = loffv;
                }
            } else {
                int n4 = nsA >> 2, rem = nsA & 3;
                for (int it = 0; it < n4; it++) {
                    FSB(0, 0, 0, 0) FSB(1, 1, 0, 1) FSB(2, 0, 0, 0) FSB(3, 0, 1, 1)
                }
                if (rem > 0) FSB(0, 0, 0, 0)
                if (rem > 1) FSB(1, 1, 0, 1)
                if (rem > 2) FSB(2, 0, 0, 0)

                if (actA) {
                    g_rv[b][cA - 1][cs] = wsh[0][cs];
                    if (tid == 0) g_roff[b][cA - 1] = loffv;
                }
            }
        }
    }

    // ================= arrival + inline stitch (last task of batch) =================
    __threadfence();
    __syncthreads();
    if (tid >= 32) return;

    const unsigned int ntasks = 1u + (unsigned)nc + (unsigned)(nc > 0 ? nc - 1 : 0);
    unsigned int old = 0;
    if (lane == 0) old = atomicAdd(&g_done[b], (unsigned)cnt);
    old = __shfl_sync(0xffffffffu, old, 0);
    if (old + (unsigned)cnt != ntasks) return;

    if (lane == 0) g_done[b] = 0;    // reset for graph replay
    __threadfence();

    float p0lo = ex2f_(potb[lane] * LOG2E);
    float p0hi = ex2f_(potb[lane + 32] * LOG2E);

    float log2A;
    if (nc == 0) {
        log2A = lg2f_(wredsum_(p0lo + p0hi));
    } else {
        float d1 = wredsum_(p0lo * g_qv[b][0][lane] + p0hi * g_qv[b][0][lane + 32]);
        log2A = lg2f_(d1) + g_qoff[b][0];
        for (int cc = 2; cc <= nc; cc++) {
            float d = wredsum_(g_rv[b][cc-2][lane]      * g_qv[b][cc-1][lane] +
                               g_rv[b][cc-2][lane + 32] * g_qv[b][cc-1][lane + 32]);
            float sig = wredsum_(g_qv[b][cc-2][lane] + g_qv[b][cc-2][lane + 32]);
            log2A += lg2f_(d) + g_roff[b][cc-2] + g_qoff[b][cc-1]
                   - lg2f_(sig) - g_qoff[b][cc-2];
        }
    }

    if (lane == 0) {
        g_partial[b] = -(g_seqs[b] - log2A * LN2) * sw[b];
        __threadfence();
    }
    __syncwarp();

    unsigned int o2 = 0;
    if (lane == 0) o2 = atomicAdd(&g_count, 1);
    o2 = __shfl_sync(0xffffffffu, o2, 0);
    if (o2 == (unsigned)B - 1) {
        if (lane == 0) { g_count = 0; __threadfence(); }
        __syncwarp();
        float tot = 0.f;
        for (int i = lane; i < B; i += 32) tot += g_partial[i];
        tot = wredsum_(tot);
        if (lane == 0) *out = tot / (float)B;
    }
}

extern "C" void kernel_launch(void* const* d_in, const int* in_sizes, int n_in,
                              void* d_out, int out_size) {
    const float* pot    = (const float*)d_in[0];
    const int*   tags   = (const int*)d_in[1];
    const int*   seqlen = (const int*)d_in[2];
    const float* K      = (const float*)d_in[3];
    const float* sw     = (const float*)d_in[4];

    int B = in_sizes[2];            // sequence_length element count
    int T = in_sizes[1] / B;        // tags is [B, T]

    crf_all_kernel<<<B * NPK, NTHR>>>(pot, tags, seqlen, K, sw, (float*)d_out, T, B);
}